// round 2
// baseline (speedup 1.0000x reference)
#include <cuda_runtime.h>

// 3x3 stride-1 pad-1 conv2d, fp32, B=16, Cin=Cout=64, H=W=256.
// Direct conv, smem-tiled, packed fma.rn.f32x2 over adjacent C_out pairs.

constexpr int C_INC  = 64;
constexpr int C_OUTC = 64;
constexpr int HH = 256;
constexpr int WW = 256;
constexpr int TH = 8;     // output rows per CTA
constexpr int TW = 32;    // output cols per CTA
constexpr int CIT = 8;    // C_in chunk held in smem
constexpr int XSTRIDE = TW + 3;  // 35: odd pad -> conflict-free LDS across rows

__device__ __forceinline__ unsigned long long dup2(float v) {
    unsigned long long r;
    asm("mov.b64 %0, {%1,%1};" : "=l"(r) : "f"(v));
    return r;
}
__device__ __forceinline__ unsigned long long fma2(unsigned long long a,
                                                   unsigned long long b,
                                                   unsigned long long c) {
    unsigned long long d;
    asm("fma.rn.f32x2 %0, %1, %2, %3;" : "=l"(d) : "l"(a), "l"(b), "l"(c));
    return d;
}
__device__ __forceinline__ void unpack2(unsigned long long v, float& lo, float& hi) {
    asm("mov.b64 {%0,%1}, %2;" : "=f"(lo), "=f"(hi) : "l"(v));
}

__global__ __launch_bounds__(256, 2)
void conv3x3_f32x2_kernel(const float* __restrict__ x,
                          const float* __restrict__ wgt,
                          const float* __restrict__ bias,
                          float* __restrict__ out)
{
    __shared__ float sx[CIT][TH + 2][XSTRIDE];   // input tile w/ halo
    __shared__ float sw[CIT][9][C_OUTC];         // weights, co contiguous

    const int tid = threadIdx.x;
    const int b   = blockIdx.z;
    const int y0  = blockIdx.y * TH;
    const int x0  = blockIdx.x * TW;

    const int cog    = tid >> 6;          // 0..3 : which 16-cout group
    const int pix    = tid & 63;          // 0..63
    const int py     = pix >> 3;          // 0..7  : row in tile
    const int pxc    = (pix & 7) << 2;    // 0,4,...,28 : col base (4 pixels)
    const int cobase = cog * 16;

    // acc[cg][j]: f32x2 pair (co = cobase+2cg, cobase+2cg+1), pixel x0+pxc+j
    unsigned long long acc[8][4];
    #pragma unroll
    for (int i = 0; i < 8; i++)
        #pragma unroll
        for (int j = 0; j < 4; j++)
            acc[i][j] = 0ull;

    const float* xb = x + (size_t)b * C_INC * (HH * WW);

    for (int ci0 = 0; ci0 < C_INC; ci0 += CIT) {
        __syncthreads();
        // ---- stage x tile (with zero halo) ----
        for (int i = tid; i < CIT * (TH + 2) * (TW + 2); i += 256) {
            int ci  = i / ((TH + 2) * (TW + 2));
            int rem = i % ((TH + 2) * (TW + 2));
            int r = rem / (TW + 2);
            int c = rem % (TW + 2);
            int gy = y0 - 1 + r;
            int gx = x0 - 1 + c;
            float v = 0.0f;
            if ((unsigned)gy < (unsigned)HH && (unsigned)gx < (unsigned)WW)
                v = xb[(size_t)(ci0 + ci) * (HH * WW) + gy * WW + gx];
            sx[ci][r][c] = v;
        }
        // ---- stage weights: sw[ci][k][co] = wgt[co][ci0+ci][k] ----
        for (int i = tid; i < CIT * 9 * C_OUTC; i += 256) {
            int co = i & 63;
            int k  = (i >> 6) % 9;
            int ci = i / (9 * 64);
            sw[ci][k][co] = wgt[(co * C_INC + ci0 + ci) * 9 + k];
        }
        __syncthreads();

        #pragma unroll 1
        for (int ci = 0; ci < CIT; ci++) {
            #pragma unroll
            for (int kh = 0; kh < 3; kh++) {
                const float* xr = &sx[ci][py + kh][pxc];
                unsigned long long xd[6];
                #pragma unroll
                for (int m = 0; m < 6; m++) xd[m] = dup2(xr[m]);

                // sw[ci][kh*3 + kw][cobase + 2cg] ; kw rows are 64 floats = 32 ull apart
                const unsigned long long* wr =
                    (const unsigned long long*)(&sw[ci][kh * 3][cobase]);
                #pragma unroll
                for (int cg = 0; cg < 8; cg++) {
                    unsigned long long w0 = wr[cg];        // kw=0, broadcast LDS.64
                    unsigned long long w1 = wr[32 + cg];   // kw=1
                    unsigned long long w2 = wr[64 + cg];   // kw=2
                    #pragma unroll
                    for (int j = 0; j < 4; j++) {
                        acc[cg][j] = fma2(w0, xd[j],     acc[cg][j]);
                        acc[cg][j] = fma2(w1, xd[j + 1], acc[cg][j]);
                        acc[cg][j] = fma2(w2, xd[j + 2], acc[cg][j]);
                    }
                }
            }
        }
    }

    // ---- epilogue: add bias, write 4-wide float4 per cout ----
    const int oy = y0 + py;
    const int ox = x0 + pxc;
    #pragma unroll
    for (int cg = 0; cg < 8; cg++) {
        int co0 = cobase + 2 * cg;
        float b0 = bias[co0], b1 = bias[co0 + 1];
        float4 v0, v1;
        float lo, hi;
        unpack2(acc[cg][0], lo, hi); v0.x = lo + b0; v1.x = hi + b1;
        unpack2(acc[cg][1], lo, hi); v0.y = lo + b0; v1.y = hi + b1;
        unpack2(acc[cg][2], lo, hi); v0.z = lo + b0; v1.z = hi + b1;
        unpack2(acc[cg][3], lo, hi); v0.w = lo + b0; v1.w = hi + b1;
        size_t base0 = (((size_t)b * C_OUTC + co0) * HH + oy) * (size_t)WW + ox;
        *(float4*)(out + base0) = v0;
        *(float4*)(out + base0 + (size_t)HH * WW) = v1;
    }
}

extern "C" void kernel_launch(void* const* d_in, const int* in_sizes, int n_in,
                              void* d_out, int out_size)
{
    const float* x    = (const float*)d_in[0];
    const float* wgt  = (const float*)d_in[1];
    const float* bias = (const float*)d_in[2];
    float* out        = (float*)d_out;

    dim3 grid(WW / TW, HH / TH, 16);   // (8, 32, 16) = 4096 CTAs
    conv3x3_f32x2_kernel<<<grid, 256>>>(x, wgt, bias, out);
}

// round 3
// speedup vs baseline: 1.0497x; 1.0497x over previous
#include <cuda_runtime.h>

// 3x3 stride-1 pad-1 conv2d, fp32, B=16, Cin=Cout=64, H=W=256.
// Direct conv, smem-tiled, packed fma.rn.f32x2 over adjacent C_out pairs.

constexpr int C_INC  = 64;
constexpr int C_OUTC = 64;
constexpr int HH = 256;
constexpr int WW = 256;
constexpr int TH = 8;     // output rows per CTA
constexpr int TW = 32;    // output cols per CTA
constexpr int CIT = 8;    // C_in chunk held in smem
constexpr int XSTRIDE = TW + 3;  // 35: odd pad -> conflict-free LDS across rows

__device__ __forceinline__ unsigned long long dup2(float v) {
    unsigned long long r;
    asm("mov.b64 %0, {%1,%1};" : "=l"(r) : "f"(v));
    return r;
}
__device__ __forceinline__ unsigned long long fma2(unsigned long long a,
                                                   unsigned long long b,
                                                   unsigned long long c) {
    unsigned long long d;
    asm("fma.rn.f32x2 %0, %1, %2, %3;" : "=l"(d) : "l"(a), "l"(b), "l"(c));
    return d;
}
__device__ __forceinline__ void unpack2(unsigned long long v, float& lo, float& hi) {
    asm("mov.b64 {%0,%1}, %2;" : "=f"(lo), "=f"(hi) : "l"(v));
}

__global__ __launch_bounds__(256, 2)
void conv3x3_f32x2_kernel(const float* __restrict__ x,
                          const float* __restrict__ wgt,
                          const float* __restrict__ bias,
                          float* __restrict__ out)
{
    __shared__ float sx[CIT][TH + 2][XSTRIDE];   // input tile w/ halo
    __shared__ float sw[CIT][9][C_OUTC];         // weights, co contiguous

    const int tid = threadIdx.x;
    const int b   = blockIdx.z;
    const int y0  = blockIdx.y * TH;
    const int x0  = blockIdx.x * TW;

    const int cog    = tid >> 6;          // 0..3 : which 16-cout group
    const int pix    = tid & 63;          // 0..63
    const int py     = pix >> 3;          // 0..7  : row in tile
    const int pxc    = (pix & 7) << 2;    // 0,4,...,28 : col base (4 pixels)
    const int cobase = cog * 16;

    // acc[cg][j]: f32x2 pair (co = cobase+2cg, cobase+2cg+1), pixel x0+pxc+j
    unsigned long long acc[8][4];
    #pragma unroll
    for (int i = 0; i < 8; i++)
        #pragma unroll
        for (int j = 0; j < 4; j++)
            acc[i][j] = 0ull;

    const float* xb = x + (size_t)b * C_INC * (HH * WW);

    for (int ci0 = 0; ci0 < C_INC; ci0 += CIT) {
        __syncthreads();
        // ---- stage x tile (with zero halo) ----
        for (int i = tid; i < CIT * (TH + 2) * (TW + 2); i += 256) {
            int ci  = i / ((TH + 2) * (TW + 2));
            int rem = i % ((TH + 2) * (TW + 2));
            int r = rem / (TW + 2);
            int c = rem % (TW + 2);
            int gy = y0 - 1 + r;
            int gx = x0 - 1 + c;
            float v = 0.0f;
            if ((unsigned)gy < (unsigned)HH && (unsigned)gx < (unsigned)WW)
                v = xb[(size_t)(ci0 + ci) * (HH * WW) + gy * WW + gx];
            sx[ci][r][c] = v;
        }
        // ---- stage weights: sw[ci][k][co] = wgt[co][ci0+ci][k] ----
        for (int i = tid; i < CIT * 9 * C_OUTC; i += 256) {
            int co = i & 63;
            int k  = (i >> 6) % 9;
            int ci = i / (9 * 64);
            sw[ci][k][co] = wgt[(co * C_INC + ci0 + ci) * 9 + k];
        }
        __syncthreads();

        #pragma unroll 1
        for (int ci = 0; ci < CIT; ci++) {
            #pragma unroll
            for (int kh = 0; kh < 3; kh++) {
                const float* xr = &sx[ci][py + kh][pxc];
                unsigned long long xd[6];
                #pragma unroll
                for (int m = 0; m < 6; m++) xd[m] = dup2(xr[m]);

                // sw[ci][kh*3 + kw][cobase + 2cg] ; kw rows are 64 floats = 32 ull apart
                const unsigned long long* wr =
                    (const unsigned long long*)(&sw[ci][kh * 3][cobase]);
                #pragma unroll
                for (int cg = 0; cg < 8; cg++) {
                    unsigned long long w0 = wr[cg];        // kw=0, broadcast LDS.64
                    unsigned long long w1 = wr[32 + cg];   // kw=1
                    unsigned long long w2 = wr[64 + cg];   // kw=2
                    #pragma unroll
                    for (int j = 0; j < 4; j++) {
                        acc[cg][j] = fma2(w0, xd[j],     acc[cg][j]);
                        acc[cg][j] = fma2(w1, xd[j + 1], acc[cg][j]);
                        acc[cg][j] = fma2(w2, xd[j + 2], acc[cg][j]);
                    }
                }
            }
        }
    }

    // ---- epilogue: add bias, write 4-wide float4 per cout ----
    const int oy = y0 + py;
    const int ox = x0 + pxc;
    #pragma unroll
    for (int cg = 0; cg < 8; cg++) {
        int co0 = cobase + 2 * cg;
        float b0 = bias[co0], b1 = bias[co0 + 1];
        float4 v0, v1;
        float lo, hi;
        unpack2(acc[cg][0], lo, hi); v0.x = lo + b0; v1.x = hi + b1;
        unpack2(acc[cg][1], lo, hi); v0.y = lo + b0; v1.y = hi + b1;
        unpack2(acc[cg][2], lo, hi); v0.z = lo + b0; v1.z = hi + b1;
        unpack2(acc[cg][3], lo, hi); v0.w = lo + b0; v1.w = hi + b1;
        size_t base0 = (((size_t)b * C_OUTC + co0) * HH + oy) * (size_t)WW + ox;
        *(float4*)(out + base0) = v0;
        *(float4*)(out + base0 + (size_t)HH * WW) = v1;
    }
}

extern "C" void kernel_launch(void* const* d_in, const int* in_sizes, int n_in,
                              void* d_out, int out_size)
{
    const float* x    = (const float*)d_in[0];
    const float* wgt  = (const float*)d_in[1];
    const float* bias = (const float*)d_in[2];
    float* out        = (float*)d_out;

    dim3 grid(WW / TW, HH / TH, 16);   // (8, 32, 16) = 4096 CTAs
    conv3x3_f32x2_kernel<<<grid, 256>>>(x, wgt, bias, out);
}

// round 6
// speedup vs baseline: 2.1490x; 2.0472x over previous
#include <cuda_runtime.h>
#include <cuda_bf16.h>
#include <cstdint>

#define DINL __device__ __forceinline__

// pre-split, pre-swizzled weights: [pass 2][tap 9][co 64][128B]
// 128B row = 8 x 16B granules: g0-3 = hi(ci 0..31 of half), g4-7 = lo; granule g stored at (g ^ (co&7))
__device__ __align__(16) unsigned char g_wsw[2 * 9 * 64 * 128];

constexpr uint32_t AROW  = 130 * 128;            // 16640 B per input row
constexpr uint32_t SA    = 0;                    // A: [3][130][128B] = 49920
constexpr uint32_t SB    = 49920;                // B: 147456
constexpr uint32_t SBAR  = 49920 + 147456;       // 197376
constexpr uint32_t SMEMSZ = SBAR + 16;

// ---------------- ptx helpers ----------------
DINL uint32_t s2u(const void* p){uint32_t a;asm("{.reg .u64 t; cvta.to.shared.u64 t,%1; cvt.u32.u64 %0,t;}":"=r"(a):"l"(p));return a;}
DINL void bar_init(uint32_t a,uint32_t c){asm volatile("mbarrier.init.shared.b64 [%0],%1;"::"r"(a),"r"(c):"memory");}
DINL void bar_expect_tx(uint32_t a,uint32_t b){asm volatile("mbarrier.arrive.expect_tx.shared.b64 _,[%0],%1;"::"r"(a),"r"(b):"memory");}
DINL void bar_wait(uint32_t a,uint32_t ph){
  uint32_t done;
  asm volatile("{.reg .pred p; mbarrier.try_wait.parity.acquire.cta.shared::cta.b64 p,[%1],%2; selp.b32 %0,1,0,p;}"
               :"=r"(done):"r"(a),"r"(ph):"memory");
  if(!done){
    asm volatile("{.reg .pred P1;\nW%=: mbarrier.try_wait.parity.acquire.cta.shared::cta.b64 P1,[%0],%1,0x989680;\n@P1 bra D%=;\nbra W%=;\nD%=:}"
                 ::"r"(a),"r"(ph):"memory");
  }
}
DINL void bulk_cp(uint32_t dst,const void* src,uint32_t bytes,uint32_t mbar){
  asm volatile("cp.async.bulk.shared::cluster.global.mbarrier::complete_tx::bytes [%0],[%1],%2,[%3];"
               ::"r"(dst),"l"(src),"r"(bytes),"r"(mbar):"memory");
}
DINL void ldsm4(uint32_t* r, uint32_t a){
  asm volatile("ldmatrix.sync.aligned.m8n8.x4.shared.b16 {%0,%1,%2,%3},[%4];"
               :"=r"(r[0]),"=r"(r[1]),"=r"(r[2]),"=r"(r[3]):"r"(a));
}
DINL void mma(float* c, const uint32_t* a, uint32_t b0, uint32_t b1){
  asm volatile("mma.sync.aligned.m16n8k16.row.col.f32.bf16.bf16.f32 "
               "{%0,%1,%2,%3},{%4,%5,%6,%7},{%8,%9},{%0,%1,%2,%3};"
               :"+f"(c[0]),"+f"(c[1]),"+f"(c[2]),"+f"(c[3])
               :"r"(a[0]),"r"(a[1]),"r"(a[2]),"r"(a[3]),"r"(b0),"r"(b1));
}
DINL uint32_t pack_bf2(float a, float b){
  __nv_bfloat16 ha = __float2bfloat16(a), hb = __float2bfloat16(b);
  return (uint32_t)__bfloat16_as_ushort(ha) | ((uint32_t)__bfloat16_as_ushort(hb) << 16);
}

// ---------------- weight prep: split + swizzle ----------------
__global__ void prep_w(const float* __restrict__ wgt){
  int tap = blockIdx.x, co = threadIdx.x;   // <<<9, 64>>>
  uint32_t sw = (uint32_t)co & 7u;
  for (int p = 0; p < 2; p++){
    unsigned char* base = g_wsw + ((size_t)(p*9 + tap)*64 + co)*128;
    for (int ci = 0; ci < 32; ci++){
      float v = wgt[co*576 + (p*32 + ci)*9 + tap];
      __nv_bfloat16 hv = __float2bfloat16(v);
      __nv_bfloat16 lv = __float2bfloat16(v - __bfloat162float(hv));
      uint32_t gh = (uint32_t)(ci >> 3), gl = gh + 4u, pos = ((uint32_t)ci & 7u)*2u;
      *(unsigned short*)(base + ((gh ^ sw) << 4) + pos) = __bfloat16_as_ushort(hv);
      *(unsigned short*)(base + ((gl ^ sw) << 4) + pos) = __bfloat16_as_ushort(lv);
    }
  }
}

// ---------------- staging helper: one (row, slot) unit ----------------
DINL void store_unit(unsigned char* smem, uint32_t addr, uint32_t swz, const float* v){
  #pragma unroll
  for (int g = 0; g < 4; g++){
    uint4 hq, lq;
    float r0, r1;
    __nv_bfloat16 t;
    // build hi and lo granules for ci = 8g..8g+7
    uint32_t hw[4], lw[4];
    #pragma unroll
    for (int j = 0; j < 4; j++){
      float a = v[g*8 + 2*j], b = v[g*8 + 2*j + 1];
      __nv_bfloat16 ha = __float2bfloat16(a), hb = __float2bfloat16(b);
      float la = a - __bfloat162float(ha), lb = b - __bfloat162float(hb);
      hw[j] = (uint32_t)__bfloat16_as_ushort(ha) | ((uint32_t)__bfloat16_as_ushort(hb) << 16);
      lw[j] = (uint32_t)__bfloat16_as_ushort(__float2bfloat16(la)) |
              ((uint32_t)__bfloat16_as_ushort(__float2bfloat16(lb)) << 16);
    }
    hq.x = hw[0]; hq.y = hw[1]; hq.z = hw[2]; hq.w = hw[3];
    lq.x = lw[0]; lq.y = lw[1]; lq.z = lw[2]; lq.w = lw[3];
    *(uint4*)(smem + addr + ((((uint32_t)g)     ^ swz) << 4)) = hq;
    *(uint4*)(smem + addr + ((((uint32_t)g + 4u) ^ swz) << 4)) = lq;
    (void)r0; (void)r1; (void)t;
  }
}

// ---------------- main kernel ----------------
__global__ __launch_bounds__(256, 1)
void conv_mma(const float* __restrict__ x,
              const float* __restrict__ bias,
              float* __restrict__ out)
{
  extern __shared__ __align__(128) unsigned char smem[];
  const uint32_t sb = s2u(smem);
  const int tid = threadIdx.x, wid = tid >> 5, lane = tid & 31;
  const int half = blockIdx.x, h = blockIdx.y, b = blockIdx.z;
  const uint32_t MB = sb + SBAR;

  if (tid == 0){
    bar_init(MB, 1);
    bar_expect_tx(MB, 147456u);
    bulk_cp(sb + SB,          g_wsw,          73728u, MB);
    bulk_cp(sb + SB + 73728u, g_wsw + 73728,  73728u, MB);
  }
  __syncthreads();

  float acc[2][8][4];
  #pragma unroll
  for (int i = 0; i < 2; i++)
    #pragma unroll
    for (int j = 0; j < 8; j++)
      #pragma unroll
      for (int k = 0; k < 4; k++) acc[i][j][k] = 0.f;

  // lane-dependent compute constants
  const uint32_t s0     = (uint32_t)(wid*32) + (uint32_t)(lane & 15);  // A slot base
  const uint32_t gha    = (uint32_t)(lane >> 4);                        // A granule half
  const uint32_t co_off = (uint32_t)((lane & 7) + (((lane >> 4) & 1) << 3));
  const uint32_t eb     = (uint32_t)(((lane >> 3) & 1) ^ (lane & 7));   // B granule xor key

  static const int AG[6] = {0, 2, 4, 6, 0, 2};
  static const int BG[6] = {0, 2, 0, 2, 4, 6};

  for (int p = 0; p < 2; p++){
    // ---- staging warps (4-7): build A = [3 rows][130 slots][hi64|lo64 bf16] ----
    if (wid >= 4){
      const int wt = tid - 128;                  // 0..127
      #pragma unroll 1
      for (int r = 0; r < 3; r++){
        int s = wt + 1;                          // slots 1..128 -> w always in range
        int y = h + r - 1;
        int w = half*128 + s - 1;
        bool vy = (unsigned)y < 256u;
        const float* xp = x + ((((size_t)b*64 + p*32)*256 + (size_t)(vy ? y : 0))*256) + w;
        float v[32];
        #pragma unroll
        for (int ci = 0; ci < 32; ci++)
          v[ci] = vy ? xp[(size_t)ci * 65536] : 0.f;
        store_unit(smem, SA + (uint32_t)r*AROW + (uint32_t)s*128u, (uint32_t)s & 7u, v);
      }
      if (wt < 6){
        int r = wt >> 1;
        int s = (wt & 1) ? 129 : 0;
        int y = h + r - 1;
        int w = half*128 + s - 1;               // -1 or 256 at batch edges
        bool ok = ((unsigned)y < 256u) && ((unsigned)w < 256u);
        const float* xp = x + ((((size_t)b*64 + p*32)*256 + (size_t)(ok ? y : 0))*256) + (ok ? w : 0);
        float v[32];
        #pragma unroll
        for (int ci = 0; ci < 32; ci++)
          v[ci] = ok ? xp[(size_t)ci * 65536] : 0.f;
        store_unit(smem, SA + (uint32_t)r*AROW + (uint32_t)s*128u, (uint32_t)s & 7u, v);
      }
    }
    __syncthreads();

    // ---- compute warps (0-3) ----
    if (wid < 4){
      if (p == 0) bar_wait(MB, 0);               // weights in smem
      const uint32_t Bp = sb + SB + (uint32_t)p * 73728u;
      #pragma unroll 1
      for (int tap = 0; tap < 9; tap++){
        const int kh = tap / 3, kw = tap - kh*3;
        const uint32_t arow = s0 + (uint32_t)kw;
        const uint32_t Aa0  = sb + SA + (uint32_t)kh*AROW + arow*128u;
        const uint32_t ea   = gha ^ (arow & 7u);
        const uint32_t Bt   = Bp + (uint32_t)tap*8192u + co_off*128u;
        #pragma unroll
        for (int ks = 0; ks < 6; ks++){
          const uint32_t bofs = (uint32_t)((BG[ks] ^ (int)eb) << 4);
          uint32_t br[16];
          ldsm4(br + 0,  Bt + bofs);
          ldsm4(br + 4,  Bt + 2048u + bofs);
          ldsm4(br + 8,  Bt + 4096u + bofs);
          ldsm4(br + 12, Bt + 6144u + bofs);
          const uint32_t aofs = (uint32_t)((AG[ks] ^ (int)ea) << 4);
          #pragma unroll
          for (int mf = 0; mf < 2; mf++){
            uint32_t ar[4];
            ldsm4(ar, Aa0 + (uint32_t)mf*2048u + aofs);
            #pragma unroll
            for (int nf = 0; nf < 8; nf++)
              mma(acc[mf][nf], ar, br[nf*2], br[nf*2 + 1]);
          }
        }
      }
    }
    __syncthreads();   // A buffer free for next pass
  }

  // ---- epilogue ----
  if (wid < 4){
    #pragma unroll
    for (int mf = 0; mf < 2; mf++){
      #pragma unroll
      for (int nf = 0; nf < 8; nf++){
        int co = nf*8 + 2*(lane & 3);
        int wo = half*128 + wid*32 + mf*16 + (lane >> 2);
        float b0 = bias[co], b1 = bias[co + 1];
        size_t o0 = (((size_t)b*64 + co)*256 + h)*256 + wo;
        out[o0]             = acc[mf][nf][0] + b0;
        out[o0 + 65536]     = acc[mf][nf][1] + b1;
        out[o0 + 8]         = acc[mf][nf][2] + b0;
        out[o0 + 65536 + 8] = acc[mf][nf][3] + b1;
      }
    }
  }
}

// ---------------- launch ----------------
extern "C" void kernel_launch(void* const* d_in, const int* in_sizes, int n_in,
                              void* d_out, int out_size)
{
  (void)in_sizes; (void)n_in; (void)out_size;
  const float* x    = (const float*)d_in[0];
  const float* wgt  = (const float*)d_in[1];
  const float* bias = (const float*)d_in[2];
  float* out        = (float*)d_out;

  cudaFuncSetAttribute(conv_mma, cudaFuncAttributeMaxDynamicSharedMemorySize, SMEMSZ);

  prep_w<<<9, 64>>>(wgt);
  dim3 grid(2, 256, 16);   // (w-half, h, b) = 8192 CTAs
  conv_mma<<<grid, 256, SMEMSZ>>>(x, bias, out);
}

// round 7
// speedup vs baseline: 2.7928x; 1.2996x over previous
#include <cuda_runtime.h>
#include <cuda_bf16.h>
#include <cstdint>

#define DINL __device__ __forceinline__

// pre-split, pre-swizzled weights: [pass 2][tap 9][co 64][128B]
// 128B row = 8 x 16B granules: g0-3 = hi(ci 0..31 of half), g4-7 = lo; granule g stored at (g ^ (co&7))
__device__ __align__(16) unsigned char g_wsw[2 * 9 * 64 * 128];

constexpr uint32_t AROW  = 130 * 128;            // 16640 B per input row
constexpr uint32_t SA    = 0;                    // A: [3][130][128B] = 49920
constexpr uint32_t SBUF  = 49920;                // B stages: 4 x 8192 = 32768
constexpr uint32_t SBAR  = 49920 + 32768;        // 82688
constexpr uint32_t SMEMSZ = SBAR + 64;           // 8 mbarriers

// ---------------- ptx helpers ----------------
DINL uint32_t s2u(const void* p){uint32_t a;asm("{.reg .u64 t; cvta.to.shared.u64 t,%1; cvt.u32.u64 %0,t;}":"=r"(a):"l"(p));return a;}
DINL void bar_init(uint32_t a,uint32_t c){asm volatile("mbarrier.init.shared.b64 [%0],%1;"::"r"(a),"r"(c):"memory");}
DINL void bar_arrive(uint32_t a){asm volatile("mbarrier.arrive.shared.b64 _,[%0];"::"r"(a):"memory");}
DINL void bar_expect_tx(uint32_t a,uint32_t b){asm volatile("mbarrier.arrive.expect_tx.shared.b64 _,[%0],%1;"::"r"(a),"r"(b):"memory");}
DINL void bar_wait(uint32_t a,uint32_t ph){
  uint32_t done;
  asm volatile("{.reg .pred p; mbarrier.try_wait.parity.acquire.cta.shared::cta.b64 p,[%1],%2; selp.b32 %0,1,0,p;}"
               :"=r"(done):"r"(a),"r"(ph):"memory");
  if(!done){
    asm volatile("{.reg .pred P1;\nW%=: mbarrier.try_wait.parity.acquire.cta.shared::cta.b64 P1,[%0],%1,0x989680;\n@P1 bra D%=;\nbra W%=;\nD%=:}"
                 ::"r"(a),"r"(ph):"memory");
  }
}
DINL void bulk_cp(uint32_t dst,const void* src,uint32_t bytes,uint32_t mbar){
  asm volatile("cp.async.bulk.shared::cluster.global.mbarrier::complete_tx::bytes [%0],[%1],%2,[%3];"
               ::"r"(dst),"l"(src),"r"(bytes),"r"(mbar):"memory");
}
DINL void ldsm4(uint32_t* r, uint32_t a){
  asm volatile("ldmatrix.sync.aligned.m8n8.x4.shared.b16 {%0,%1,%2,%3},[%4];"
               :"=r"(r[0]),"=r"(r[1]),"=r"(r[2]),"=r"(r[3]):"r"(a));
}
DINL void mma(float* c, const uint32_t* a, uint32_t b0, uint32_t b1){
  asm volatile("mma.sync.aligned.m16n8k16.row.col.f32.bf16.bf16.f32 "
               "{%0,%1,%2,%3},{%4,%5,%6,%7},{%8,%9},{%0,%1,%2,%3};"
               :"+f"(c[0]),"+f"(c[1]),"+f"(c[2]),"+f"(c[3])
               :"r"(a[0]),"r"(a[1]),"r"(a[2]),"r"(a[3]),"r"(b0),"r"(b1));
}

// ---------------- weight prep: split + swizzle ----------------
__global__ void prep_w(const float* __restrict__ wgt){
  int tap = blockIdx.x, co = threadIdx.x;   // <<<9, 64>>>
  uint32_t sw = (uint32_t)co & 7u;
  for (int p = 0; p < 2; p++){
    unsigned char* base = g_wsw + ((size_t)(p*9 + tap)*64 + co)*128;
    for (int ci = 0; ci < 32; ci++){
      float v = wgt[co*576 + (p*32 + ci)*9 + tap];
      __nv_bfloat16 hv = __float2bfloat16(v);
      __nv_bfloat16 lv = __float2bfloat16(v - __bfloat162float(hv));
      uint32_t gh = (uint32_t)(ci >> 3), gl = gh + 4u, pos = ((uint32_t)ci & 7u)*2u;
      *(unsigned short*)(base + ((gh ^ sw) << 4) + pos) = __bfloat16_as_ushort(hv);
      *(unsigned short*)(base + ((gl ^ sw) << 4) + pos) = __bfloat16_as_ushort(lv);
    }
  }
}

// ---------------- staging helper: one (row, slot) unit ----------------
DINL void store_unit(unsigned char* smem, uint32_t addr, uint32_t swz, const float* v){
  #pragma unroll
  for (int g = 0; g < 4; g++){
    uint4 hq, lq;
    uint32_t hw[4], lw[4];
    #pragma unroll
    for (int j = 0; j < 4; j++){
      float a = v[g*8 + 2*j], b = v[g*8 + 2*j + 1];
      __nv_bfloat16 ha = __float2bfloat16(a), hb = __float2bfloat16(b);
      float la = a - __bfloat162float(ha), lb = b - __bfloat162float(hb);
      hw[j] = (uint32_t)__bfloat16_as_ushort(ha) | ((uint32_t)__bfloat16_as_ushort(hb) << 16);
      lw[j] = (uint32_t)__bfloat16_as_ushort(__float2bfloat16(la)) |
              ((uint32_t)__bfloat16_as_ushort(__float2bfloat16(lb)) << 16);
    }
    hq.x = hw[0]; hq.y = hw[1]; hq.z = hw[2]; hq.w = hw[3];
    lq.x = lw[0]; lq.y = lw[1]; lq.z = lw[2]; lq.w = lw[3];
    *(uint4*)(smem + addr + ((((uint32_t)g)      ^ swz) << 4)) = hq;
    *(uint4*)(smem + addr + ((((uint32_t)g + 4u) ^ swz) << 4)) = lq;
  }
}

// ---------------- main kernel ----------------
__global__ __launch_bounds__(256, 2)
void conv_mma(const float* __restrict__ x,
              const float* __restrict__ bias,
              float* __restrict__ out)
{
  extern __shared__ __align__(128) unsigned char smem[];
  const uint32_t sb = s2u(smem);
  const int tid = threadIdx.x, wid = tid >> 5, lane = tid & 31;
  const int half = blockIdx.x, h = blockIdx.y, b = blockIdx.z;

  // barriers: FULL[0..3], EMPTY[0..3]
  const uint32_t BARB = sb + SBAR;

  if (tid == 0){
    #pragma unroll
    for (int s = 0; s < 4; s++){
      bar_init(BARB + s*8, 1);          // full: tx-based
      bar_init(BARB + 32 + s*8, 4);     // empty: 4 compute warps
    }
  }
  __syncthreads();
  if (tid == 0){
    #pragma unroll
    for (int s = 0; s < 4; s++){
      bar_expect_tx(BARB + s*8, 8192u);
      bulk_cp(sb + SBUF + (uint32_t)s*8192u, g_wsw + (size_t)s*8192, 8192u, BARB + s*8);
    }
  }

  float acc[2][8][4];
  #pragma unroll
  for (int i = 0; i < 2; i++)
    #pragma unroll
    for (int j = 0; j < 8; j++)
      #pragma unroll
      for (int k = 0; k < 4; k++) acc[i][j][k] = 0.f;

  // lane-dependent compute constants
  const uint32_t s0     = (uint32_t)(wid*32) + (uint32_t)(lane & 15);  // A slot base
  const uint32_t gha    = (uint32_t)(lane >> 4);                        // A granule half
  const uint32_t co_off = (uint32_t)((lane & 7) + (((lane >> 4) & 1) << 3));
  const uint32_t eb     = (uint32_t)(((lane >> 3) & 1) ^ (lane & 7));   // B granule xor key

  static const int AG[6] = {0, 2, 4, 6, 0, 2};
  static const int BG[6] = {0, 2, 0, 2, 4, 6};

  for (int p = 0; p < 2; p++){
    // ---- staging warps (4-7): build A = [3 rows][130 slots][hi64|lo64 bf16] ----
    if (wid >= 4){
      const int wt = tid - 128;                  // 0..127
      #pragma unroll 1
      for (int r = 0; r < 3; r++){
        int s = wt + 1;                          // slots 1..128 -> w always in range
        int y = h + r - 1;
        int w = half*128 + s - 1;
        bool vy = (unsigned)y < 256u;
        const float* xp = x + ((((size_t)b*64 + p*32)*256 + (size_t)(vy ? y : 0))*256) + w;
        float v[32];
        #pragma unroll
        for (int ci = 0; ci < 32; ci++)
          v[ci] = vy ? xp[(size_t)ci * 65536] : 0.f;
        store_unit(smem, SA + (uint32_t)r*AROW + (uint32_t)s*128u, (uint32_t)s & 7u, v);
      }
      if (wt < 6){
        int r = wt >> 1;
        int s = (wt & 1) ? 129 : 0;
        int y = h + r - 1;
        int w = half*128 + s - 1;               // -1 or 256 at batch edges
        bool ok = ((unsigned)y < 256u) && ((unsigned)w < 256u);
        const float* xp = x + ((((size_t)b*64 + p*32)*256 + (size_t)(ok ? y : 0))*256) + (ok ? w : 0);
        float v[32];
        #pragma unroll
        for (int ci = 0; ci < 32; ci++)
          v[ci] = ok ? xp[(size_t)ci * 65536] : 0.f;
        store_unit(smem, SA + (uint32_t)r*AROW + (uint32_t)s*128u, (uint32_t)s & 7u, v);
      }
    }
    __syncthreads();

    // ---- compute warps (0-3) ----
    if (wid < 4){
      #pragma unroll 1
      for (int tap = 0; tap < 9; tap++){
        const int it = p*9 + tap;
        const int st = it & 3;
        const uint32_t fullb  = BARB + (uint32_t)st*8u;
        const uint32_t emptyb = BARB + 32u + (uint32_t)st*8u;
        bar_wait(fullb, (uint32_t)((it >> 2) & 1));

        const int kh = tap / 3, kw = tap - kh*3;
        const uint32_t arow = s0 + (uint32_t)kw;
        const uint32_t Aa0  = sb + SA + (uint32_t)kh*AROW + arow*128u;
        const uint32_t ea   = gha ^ (arow & 7u);
        const uint32_t Bt   = sb + SBUF + (uint32_t)st*8192u + co_off*128u;
        #pragma unroll
        for (int ks = 0; ks < 6; ks++){
          const uint32_t bofs = (uint32_t)((BG[ks] ^ (int)eb) << 4);
          uint32_t br[16];
          ldsm4(br + 0,  Bt + bofs);
          ldsm4(br + 4,  Bt + 2048u + bofs);
          ldsm4(br + 8,  Bt + 4096u + bofs);
          ldsm4(br + 12, Bt + 6144u + bofs);
          const uint32_t aofs = (uint32_t)((AG[ks] ^ (int)ea) << 4);
          #pragma unroll
          for (int mf = 0; mf < 2; mf++){
            uint32_t ar[4];
            ldsm4(ar, Aa0 + (uint32_t)mf*2048u + aofs);
            #pragma unroll
            for (int nf = 0; nf < 8; nf++)
              mma(acc[mf][nf], ar, br[nf*2], br[nf*2 + 1]);
          }
        }

        if (lane == 0) bar_arrive(emptyb);
        if (wid == 0 && lane == 0 && it < 14){
          // refill this stage with iteration it+4 after all 4 warps released it
          bar_wait(emptyb, (uint32_t)((it >> 2) & 1));
          bar_expect_tx(fullb, 8192u);
          bulk_cp(sb + SBUF + (uint32_t)st*8192u,
                  g_wsw + (size_t)(it + 4)*8192, 8192u, fullb);
        }
      }
    }
    __syncthreads();   // A buffer free for next pass
  }

  // ---- epilogue ----
  if (wid < 4){
    #pragma unroll
    for (int mf = 0; mf < 2; mf++){
      #pragma unroll
      for (int nf = 0; nf < 8; nf++){
        int co = nf*8 + 2*(lane & 3);
        int wo = half*128 + wid*32 + mf*16 + (lane >> 2);
        float b0 = bias[co], b1 = bias[co + 1];
        size_t o0 = (((size_t)b*64 + co)*256 + h)*256 + wo;
        out[o0]             = acc[mf][nf][0] + b0;
        out[o0 + 65536]     = acc[mf][nf][1] + b1;
        out[o0 + 8]         = acc[mf][nf][2] + b0;
        out[o0 + 65536 + 8] = acc[mf][nf][3] + b1;
      }
    }
  }
}

// ---------------- launch ----------------
extern "C" void kernel_launch(void* const* d_in, const int* in_sizes, int n_in,
                              void* d_out, int out_size)
{
  (void)in_sizes; (void)n_in; (void)out_size;
  const float* x    = (const float*)d_in[0];
  const float* wgt  = (const float*)d_in[1];
  const float* bias = (const float*)d_in[2];
  float* out        = (float*)d_out;

  cudaFuncSetAttribute(conv_mma, cudaFuncAttributeMaxDynamicSharedMemorySize, SMEMSZ);

  prep_w<<<9, 64>>>(wgt);
  dim3 grid(2, 256, 16);   // (w-half, h, b) = 8192 CTAs
  conv_mma<<<grid, 256, SMEMSZ>>>(x, bias, out);
}

// round 8
// speedup vs baseline: 4.0444x; 1.4481x over previous
#include <cuda_runtime.h>
#include <cuda_bf16.h>
#include <cstdint>

#define DINL __device__ __forceinline__

// pre-rounded tf32 weights: [pass 2][tap 9][n=co 64][128B]
// 128B row = 32 tf32 (k=ci of pass); 8 x 16B granules, granule g (k 4g..4g+3) stored at (g ^ (n&7))
__device__ __align__(16) unsigned char g_wsw[2 * 9 * 64 * 128];

constexpr uint32_t AROW  = 130 * 128;            // 16640 B per input row
constexpr uint32_t SA    = 0;                    // A: [3][130][128B] = 49920
constexpr uint32_t SBUF  = 49920;                // B stages: 4 x 8192 = 32768
constexpr uint32_t SBAR  = 49920 + 32768;        // 82688
constexpr uint32_t SMEMSZ = SBAR + 64;           // 8 mbarriers

// ---------------- ptx helpers ----------------
DINL uint32_t s2u(const void* p){uint32_t a;asm("{.reg .u64 t; cvta.to.shared.u64 t,%1; cvt.u32.u64 %0,t;}":"=r"(a):"l"(p));return a;}
DINL void bar_init(uint32_t a,uint32_t c){asm volatile("mbarrier.init.shared.b64 [%0],%1;"::"r"(a),"r"(c):"memory");}
DINL void bar_arrive(uint32_t a){asm volatile("mbarrier.arrive.shared.b64 _,[%0];"::"r"(a):"memory");}
DINL void bar_expect_tx(uint32_t a,uint32_t b){asm volatile("mbarrier.arrive.expect_tx.shared.b64 _,[%0],%1;"::"r"(a),"r"(b):"memory");}
DINL void bar_wait(uint32_t a,uint32_t ph){
  uint32_t done;
  asm volatile("{.reg .pred p; mbarrier.try_wait.parity.acquire.cta.shared::cta.b64 p,[%1],%2; selp.b32 %0,1,0,p;}"
               :"=r"(done):"r"(a),"r"(ph):"memory");
  if(!done){
    asm volatile("{.reg .pred P1;\nW%=: mbarrier.try_wait.parity.acquire.cta.shared::cta.b64 P1,[%0],%1,0x989680;\n@P1 bra D%=;\nbra W%=;\nD%=:}"
                 ::"r"(a),"r"(ph):"memory");
  }
}
DINL void bulk_cp(uint32_t dst,const void* src,uint32_t bytes,uint32_t mbar){
  asm volatile("cp.async.bulk.shared::cluster.global.mbarrier::complete_tx::bytes [%0],[%1],%2,[%3];"
               ::"r"(dst),"l"(src),"r"(bytes),"r"(mbar):"memory");
}
DINL void ldsm4(uint32_t* r, uint32_t a){
  asm volatile("ldmatrix.sync.aligned.m8n8.x4.shared.b16 {%0,%1,%2,%3},[%4];"
               :"=r"(r[0]),"=r"(r[1]),"=r"(r[2]),"=r"(r[3]):"r"(a));
}
DINL void mma(float* c, const uint32_t* a, uint32_t b0, uint32_t b1){
  asm volatile("mma.sync.aligned.m16n8k8.row.col.f32.tf32.tf32.f32 "
               "{%0,%1,%2,%3},{%4,%5,%6,%7},{%8,%9},{%0,%1,%2,%3};"
               :"+f"(c[0]),"+f"(c[1]),"+f"(c[2]),"+f"(c[3])
               :"r"(a[0]),"r"(a[1]),"r"(a[2]),"r"(a[3]),"r"(b0),"r"(b1));
}
DINL uint32_t f2tf(float f){uint32_t u;asm("cvt.rna.tf32.f32 %0,%1;":"=r"(u):"f"(f));return u;}

// ---------------- weight prep: tf32 round + swizzle ----------------
__global__ void prep_w(const float* __restrict__ wgt){
  int tap = blockIdx.x, co = threadIdx.x;   // <<<9, 64>>>
  uint32_t sw = (uint32_t)co & 7u;
  for (int p = 0; p < 2; p++){
    unsigned char* base = g_wsw + ((size_t)(p*9 + tap)*64 + co)*128;
    for (int k = 0; k < 32; k++){
      float v = wgt[co*576 + (p*32 + k)*9 + tap];
      uint32_t g = (uint32_t)(k >> 2), pos = ((uint32_t)k & 3u)*4u;
      *(uint32_t*)(base + ((g ^ sw) << 4) + pos) = f2tf(v);
    }
  }
}

// ---------------- staging helper: one (row, slot) unit ----------------
DINL void store_unit(unsigned char* smem, uint32_t addr, uint32_t swz, const float* v){
  #pragma unroll
  for (int g = 0; g < 8; g++){
    uint4 q;
    q.x = f2tf(v[g*4 + 0]);
    q.y = f2tf(v[g*4 + 1]);
    q.z = f2tf(v[g*4 + 2]);
    q.w = f2tf(v[g*4 + 3]);
    *(uint4*)(smem + addr + ((((uint32_t)g) ^ swz) << 4)) = q;
  }
}

// ---------------- main kernel ----------------
__global__ __launch_bounds__(256, 2)
void conv_mma(const float* __restrict__ x,
              const float* __restrict__ bias,
              float* __restrict__ out)
{
  extern __shared__ __align__(128) unsigned char smem[];
  const uint32_t sb = s2u(smem);
  const int tid = threadIdx.x, wid = tid >> 5, lane = tid & 31;
  const int half = blockIdx.x, h = blockIdx.y, b = blockIdx.z;

  // barriers: FULL[0..3], EMPTY[0..3]
  const uint32_t BARB = sb + SBAR;

  if (tid == 0){
    #pragma unroll
    for (int s = 0; s < 4; s++){
      bar_init(BARB + s*8, 1);          // full: tx-based
      bar_init(BARB + 32 + s*8, 4);     // empty: 4 compute warps
    }
  }
  __syncthreads();
  if (tid == 0){
    #pragma unroll
    for (int s = 0; s < 4; s++){
      bar_expect_tx(BARB + s*8, 8192u);
      bulk_cp(sb + SBUF + (uint32_t)s*8192u, g_wsw + (size_t)s*8192, 8192u, BARB + s*8);
    }
  }

  float acc[2][8][4];
  #pragma unroll
  for (int i = 0; i < 2; i++)
    #pragma unroll
    for (int j = 0; j < 8; j++)
      #pragma unroll
      for (int k = 0; k < 4; k++) acc[i][j][k] = 0.f;

  // lane-dependent compute constants (identical structure to bf16 version)
  const uint32_t s0     = (uint32_t)(wid*32) + (uint32_t)(lane & 15);  // A slot base
  const uint32_t gha    = (uint32_t)(lane >> 4);                        // A granule select
  const uint32_t co_off = (uint32_t)((lane & 7) + (((lane >> 4) & 1) << 3));
  const uint32_t eb     = (uint32_t)(((lane >> 3) & 1) ^ (lane & 7));   // B granule xor key

  for (int p = 0; p < 2; p++){
    // ---- staging warps (4-7): build A = [3 rows][130 slots][32 tf32] ----
    if (wid >= 4){
      const int wt = tid - 128;                  // 0..127
      #pragma unroll 1
      for (int r = 0; r < 3; r++){
        int s = wt + 1;                          // slots 1..128 -> w always in range
        int y = h + r - 1;
        int w = half*128 + s - 1;
        bool vy = (unsigned)y < 256u;
        const float* xp = x + ((((size_t)b*64 + p*32)*256 + (size_t)(vy ? y : 0))*256) + w;
        float v[32];
        #pragma unroll
        for (int ci = 0; ci < 32; ci++)
          v[ci] = vy ? xp[(size_t)ci * 65536] : 0.f;
        store_unit(smem, SA + (uint32_t)r*AROW + (uint32_t)s*128u, (uint32_t)s & 7u, v);
      }
      if (wt < 6){
        int r = wt >> 1;
        int s = (wt & 1) ? 129 : 0;
        int y = h + r - 1;
        int w = half*128 + s - 1;               // -1 or 256 at batch edges
        bool ok = ((unsigned)y < 256u) && ((unsigned)w < 256u);
        const float* xp = x + ((((size_t)b*64 + p*32)*256 + (size_t)(ok ? y : 0))*256) + (ok ? w : 0);
        float v[32];
        #pragma unroll
        for (int ci = 0; ci < 32; ci++)
          v[ci] = ok ? xp[(size_t)ci * 65536] : 0.f;
        store_unit(smem, SA + (uint32_t)r*AROW + (uint32_t)s*128u, (uint32_t)s & 7u, v);
      }
    }
    __syncthreads();

    // ---- compute warps (0-3) ----
    if (wid < 4){
      #pragma unroll 1
      for (int tap = 0; tap < 9; tap++){
        const int it = p*9 + tap;
        const int st = it & 3;
        const uint32_t fullb  = BARB + (uint32_t)st*8u;
        const uint32_t emptyb = BARB + 32u + (uint32_t)st*8u;
        bar_wait(fullb, (uint32_t)((it >> 2) & 1));

        const int kh = tap / 3, kw = tap - kh*3;
        const uint32_t arow = s0 + (uint32_t)kw;
        const uint32_t Aa0  = sb + SA + (uint32_t)kh*AROW + arow*128u;
        const uint32_t ea   = gha ^ (arow & 7u);
        const uint32_t Bt   = sb + SBUF + (uint32_t)st*8192u + co_off*128u;
        #pragma unroll
        for (int ks = 0; ks < 4; ks++){
          const uint32_t bofs = (uint32_t)(((2*ks) ^ (int)eb) << 4);
          uint32_t br[16];
          ldsm4(br + 0,  Bt + bofs);
          ldsm4(br + 4,  Bt + 2048u + bofs);
          ldsm4(br + 8,  Bt + 4096u + bofs);
          ldsm4(br + 12, Bt + 6144u + bofs);
          const uint32_t aofs = (uint32_t)(((2*ks) ^ (int)ea) << 4);
          #pragma unroll
          for (int mf = 0; mf < 2; mf++){
            uint32_t ar[4];
            ldsm4(ar, Aa0 + (uint32_t)mf*2048u + aofs);
            #pragma unroll
            for (int nf = 0; nf < 8; nf++)
              mma(acc[mf][nf], ar, br[nf*2], br[nf*2 + 1]);
          }
        }

        if (lane == 0) bar_arrive(emptyb);
        if (wid == 0 && lane == 0 && it < 14){
          // refill this stage with iteration it+4 after all 4 warps released it
          bar_wait(emptyb, (uint32_t)((it >> 2) & 1));
          bar_expect_tx(fullb, 8192u);
          bulk_cp(sb + SBUF + (uint32_t)st*8192u,
                  g_wsw + (size_t)(it + 4)*8192, 8192u, fullb);
        }
      }
    }
    __syncthreads();   // A buffer free for next pass
  }

  // ---- epilogue ----
  if (wid < 4){
    #pragma unroll
    for (int mf = 0; mf < 2; mf++){
      #pragma unroll
      for (int nf = 0; nf < 8; nf++){
        int co = nf*8 + 2*(lane & 3);
        int wo = half*128 + wid*32 + mf*16 + (lane >> 2);
        float b0 = bias[co], b1 = bias[co + 1];
        size_t o0 = (((size_t)b*64 + co)*256 + h)*256 + wo;
        out[o0]             = acc[mf][nf][0] + b0;
        out[o0 + 65536]     = acc[mf][nf][1] + b1;
        out[o0 + 8]         = acc[mf][nf][2] + b0;
        out[o0 + 65536 + 8] = acc[mf][nf][3] + b1;
      }
    }
  }
}

// ---------------- launch ----------------
extern "C" void kernel_launch(void* const* d_in, const int* in_sizes, int n_in,
                              void* d_out, int out_size)
{
  (void)in_sizes; (void)n_in; (void)out_size;
  const float* x    = (const float*)d_in[0];
  const float* wgt  = (const float*)d_in[1];
  const float* bias = (const float*)d_in[2];
  float* out        = (float*)d_out;

  cudaFuncSetAttribute(conv_mma, cudaFuncAttributeMaxDynamicSharedMemorySize, SMEMSZ);

  prep_w<<<9, 64>>>(wgt);
  dim3 grid(2, 256, 16);   // (w-half, h, b) = 8192 CTAs
  conv_mma<<<grid, 256, SMEMSZ>>>(x, bias, out);
}

// round 9
// speedup vs baseline: 4.6338x; 1.1457x over previous
#include <cuda_runtime.h>
#include <cuda_bf16.h>
#include <cstdint>

#define DINL __device__ __forceinline__

// pre-rounded tf32 weights: [pass 2][tap 9][n=co 64][128B]
// 128B row = 32 tf32 (k=ci of pass); 8 x 16B granules, granule g stored at (g ^ (n&7))
__device__ __align__(16) unsigned char g_wsw[2 * 9 * 64 * 128];

constexpr uint32_t AROWSZ = 130 * 128;           // 16640 B per staged input row
constexpr uint32_t SA    = 0;                    // A ring: 4 x 16640 = 66560
constexpr uint32_t SBUF  = 66560;                // B stages: 4 x 8192 = 32768
constexpr uint32_t SBAR  = 66560 + 32768;        // 99328
constexpr uint32_t SMEMSZ = SBAR + 128;          // 16 mbarriers

// ---------------- ptx helpers ----------------
DINL uint32_t s2u(const void* p){uint32_t a;asm("{.reg .u64 t; cvta.to.shared.u64 t,%1; cvt.u32.u64 %0,t;}":"=r"(a):"l"(p));return a;}
DINL void bar_init(uint32_t a,uint32_t c){asm volatile("mbarrier.init.shared.b64 [%0],%1;"::"r"(a),"r"(c):"memory");}
DINL void bar_arrive(uint32_t a){asm volatile("mbarrier.arrive.shared.b64 _,[%0];"::"r"(a):"memory");}
DINL void bar_expect_tx(uint32_t a,uint32_t b){asm volatile("mbarrier.arrive.expect_tx.shared.b64 _,[%0],%1;"::"r"(a),"r"(b):"memory");}
DINL void bar_wait(uint32_t a,uint32_t ph){
  uint32_t done;
  asm volatile("{.reg .pred p; mbarrier.try_wait.parity.acquire.cta.shared::cta.b64 p,[%1],%2; selp.b32 %0,1,0,p;}"
               :"=r"(done):"r"(a),"r"(ph):"memory");
  if(!done){
    asm volatile("{.reg .pred P1;\nW%=: mbarrier.try_wait.parity.acquire.cta.shared::cta.b64 P1,[%0],%1,0x989680;\n@P1 bra D%=;\nbra W%=;\nD%=:}"
                 ::"r"(a),"r"(ph):"memory");
  }
}
DINL void bulk_cp(uint32_t dst,const void* src,uint32_t bytes,uint32_t mbar){
  asm volatile("cp.async.bulk.shared::cluster.global.mbarrier::complete_tx::bytes [%0],[%1],%2,[%3];"
               ::"r"(dst),"l"(src),"r"(bytes),"r"(mbar):"memory");
}
DINL void ldsm4(uint32_t* r, uint32_t a){
  asm volatile("ldmatrix.sync.aligned.m8n8.x4.shared.b16 {%0,%1,%2,%3},[%4];"
               :"=r"(r[0]),"=r"(r[1]),"=r"(r[2]),"=r"(r[3]):"r"(a));
}
DINL void mma(float* c, const uint32_t* a, uint32_t b0, uint32_t b1){
  asm volatile("mma.sync.aligned.m16n8k8.row.col.f32.tf32.tf32.f32 "
               "{%0,%1,%2,%3},{%4,%5,%6,%7},{%8,%9},{%0,%1,%2,%3};"
               :"+f"(c[0]),"+f"(c[1]),"+f"(c[2]),"+f"(c[3])
               :"r"(a[0]),"r"(a[1]),"r"(a[2]),"r"(a[3]),"r"(b0),"r"(b1));
}
DINL uint32_t f2tf(float f){uint32_t u;asm("cvt.rna.tf32.f32 %0,%1;":"=r"(u):"f"(f));return u;}

// ---------------- weight prep: tf32 round + swizzle ----------------
__global__ void prep_w(const float* __restrict__ wgt){
  int tap = blockIdx.x, co = threadIdx.x;   // <<<9, 64>>>
  uint32_t sw = (uint32_t)co & 7u;
  for (int p = 0; p < 2; p++){
    unsigned char* base = g_wsw + ((size_t)(p*9 + tap)*64 + co)*128;
    for (int k = 0; k < 32; k++){
      float v = wgt[co*576 + (p*32 + k)*9 + tap];
      uint32_t g = (uint32_t)(k >> 2), pos = ((uint32_t)k & 3u)*4u;
      *(uint32_t*)(base + ((g ^ sw) << 4) + pos) = f2tf(v);
    }
  }
}

// ---------------- staging helper: one slot (32 tf32, swizzled) ----------------
DINL void store_unit(unsigned char* smem, uint32_t addr, uint32_t swz, const float* v){
  #pragma unroll
  for (int g = 0; g < 8; g++){
    uint4 q;
    q.x = f2tf(v[g*4 + 0]);
    q.y = f2tf(v[g*4 + 1]);
    q.z = f2tf(v[g*4 + 2]);
    q.w = f2tf(v[g*4 + 3]);
    *(uint4*)(smem + addr + ((((uint32_t)g) ^ swz) << 4)) = q;
  }
}

// ---------------- main kernel ----------------
__global__ __launch_bounds__(256, 2)
void conv_mma(const float* __restrict__ x,
              const float* __restrict__ bias,
              float* __restrict__ out)
{
  extern __shared__ __align__(128) unsigned char smem[];
  const uint32_t sb = s2u(smem);
  const int tid = threadIdx.x, wid = tid >> 5, lane = tid & 31;
  const int half = blockIdx.x, h = blockIdx.y, b = blockIdx.z;

  // barriers: BFULL[0..3]@+0, BEMPTY[0..3]@+32, AFULL[0..3]@+64, AEMPTY[0..3]@+96
  const uint32_t BARB = sb + SBAR;

  if (tid == 0){
    #pragma unroll
    for (int s = 0; s < 4; s++){
      bar_init(BARB + s*8, 1);            // B full: tx-based
      bar_init(BARB + 32 + s*8, 4);       // B empty: 4 compute warps (lane 0)
      bar_init(BARB + 64 + s*8, 128);     // A full: 128 staging threads
      bar_init(BARB + 96 + s*8, 128);     // A empty: 128 compute threads
    }
  }
  __syncthreads();
  if (tid == 0){
    #pragma unroll
    for (int s = 0; s < 4; s++){
      bar_expect_tx(BARB + s*8, 8192u);
      bulk_cp(sb + SBUF + (uint32_t)s*8192u, g_wsw + (size_t)s*8192, 8192u, BARB + s*8);
    }
  }

  if (wid >= 4){
    // ---------------- staging warps (4-7): row ring producer ----------------
    const int wt = tid - 128;                  // 0..127
    #pragma unroll 1
    for (int r = 0; r < 6; r++){               // r = p*3 + kh
      const int p = (r >= 3) ? 1 : 0;
      const int khr = r - 3*p;
      const int slot = r & 3;
      if (r >= 4) bar_wait(BARB + 96u + (uint32_t)slot*8u, 0);
      const uint32_t Abase = SA + (uint32_t)slot*AROWSZ;
      const int y = h + khr - 1;
      const bool vy = (unsigned)y < 256u;
      // main slot: s = wt+1 (w always in-range)
      {
        int s = wt + 1;
        int w = half*128 + s - 1;
        const float* xp = x + ((((size_t)b*64 + p*32)*256 + (size_t)(vy ? y : 0))*256) + w;
        float v[32];
        #pragma unroll
        for (int ci = 0; ci < 32; ci++)
          v[ci] = vy ? xp[(size_t)ci * 65536] : 0.f;
        store_unit(smem, Abase + (uint32_t)s*128u, (uint32_t)s & 7u, v);
      }
      // edge slots 0 and 129
      if (wt == 0 || wt == 127){
        int s = (wt == 0) ? 0 : 129;
        int w = half*128 + s - 1;
        bool ok = vy && ((unsigned)w < 256u);
        const float* xp = x + ((((size_t)b*64 + p*32)*256 + (size_t)(ok ? y : 0))*256) + (ok ? w : 0);
        float v[32];
        #pragma unroll
        for (int ci = 0; ci < 32; ci++)
          v[ci] = ok ? xp[(size_t)ci * 65536] : 0.f;
        store_unit(smem, Abase + (uint32_t)s*128u, (uint32_t)s & 7u, v);
      }
      bar_arrive(BARB + 64u + (uint32_t)slot*8u);   // A full (release)
    }
  } else {
    // ---------------- compute warps (0-3) ----------------
    float acc[2][8][4];
    #pragma unroll
    for (int i = 0; i < 2; i++)
      #pragma unroll
      for (int j = 0; j < 8; j++)
        #pragma unroll
        for (int k = 0; k < 4; k++) acc[i][j][k] = 0.f;

    const uint32_t s0     = (uint32_t)(wid*32) + (uint32_t)(lane & 15);  // A slot base
    const uint32_t gha    = (uint32_t)(lane >> 4);                        // A granule select
    const uint32_t co_off = (uint32_t)((lane & 7) + (((lane >> 4) & 1) << 3));
    const uint32_t eb     = (uint32_t)(((lane >> 3) & 1) ^ (lane & 7));   // B granule xor key

    #pragma unroll 1
    for (int r = 0; r < 6; r++){               // r = p*3 + kh
      const int slot = r & 3;
      bar_wait(BARB + 64u + (uint32_t)slot*8u, (uint32_t)((r >> 2) & 1));
      const uint32_t Aslot = sb + SA + (uint32_t)slot*AROWSZ;

      #pragma unroll 1
      for (int kw = 0; kw < 3; kw++){
        const int it = r*3 + kw;               // linear tap-pass index 0..17
        const int st = it & 3;
        const uint32_t fullb  = BARB + (uint32_t)st*8u;
        const uint32_t emptyb = BARB + 32u + (uint32_t)st*8u;
        bar_wait(fullb, (uint32_t)((it >> 2) & 1));

        const uint32_t arow = s0 + (uint32_t)kw;
        const uint32_t Aa0  = Aslot + arow*128u;
        const uint32_t ea   = gha ^ (arow & 7u);
        const uint32_t Bt   = sb + SBUF + (uint32_t)st*8192u + co_off*128u;
        #pragma unroll
        for (int ks = 0; ks < 4; ks++){
          const uint32_t bofs = (uint32_t)(((2*ks) ^ (int)eb) << 4);
          uint32_t br[16];
          ldsm4(br + 0,  Bt + bofs);
          ldsm4(br + 4,  Bt + 2048u + bofs);
          ldsm4(br + 8,  Bt + 4096u + bofs);
          ldsm4(br + 12, Bt + 6144u + bofs);
          const uint32_t aofs = (uint32_t)(((2*ks) ^ (int)ea) << 4);
          #pragma unroll
          for (int mf = 0; mf < 2; mf++){
            uint32_t ar[4];
            ldsm4(ar, Aa0 + (uint32_t)mf*2048u + aofs);
            #pragma unroll
            for (int nf = 0; nf < 8; nf++)
              mma(acc[mf][nf], ar, br[nf*2], br[nf*2 + 1]);
          }
        }

        if (lane == 0) bar_arrive(emptyb);
        if (wid == 0 && lane == 0 && it < 14){
          bar_wait(emptyb, (uint32_t)((it >> 2) & 1));
          bar_expect_tx(fullb, 8192u);
          bulk_cp(sb + SBUF + (uint32_t)st*8192u,
                  g_wsw + (size_t)(it + 4)*8192, 8192u, fullb);
        }
      }
      bar_arrive(BARB + 96u + (uint32_t)slot*8u);   // A empty (release row)
    }

    // ---- epilogue ----
    #pragma unroll
    for (int mf = 0; mf < 2; mf++){
      #pragma unroll
      for (int nf = 0; nf < 8; nf++){
        int co = nf*8 + 2*(lane & 3);
        int wo = half*128 + wid*32 + mf*16 + (lane >> 2);
        float b0 = bias[co], b1 = bias[co + 1];
        size_t o0 = (((size_t)b*64 + co)*256 + h)*256 + wo;
        out[o0]             = acc[mf][nf][0] + b0;
        out[o0 + 65536]     = acc[mf][nf][1] + b1;
        out[o0 + 8]         = acc[mf][nf][2] + b0;
        out[o0 + 65536 + 8] = acc[mf][nf][3] + b1;
      }
    }
  }
}

// ---------------- launch ----------------
extern "C" void kernel_launch(void* const* d_in, const int* in_sizes, int n_in,
                              void* d_out, int out_size)
{
  (void)in_sizes; (void)n_in; (void)out_size;
  const float* x    = (const float*)d_in[0];
  const float* wgt  = (const float*)d_in[1];
  const float* bias = (const float*)d_in[2];
  float* out        = (float*)d_out;

  cudaFuncSetAttribute(conv_mma, cudaFuncAttributeMaxDynamicSharedMemorySize, SMEMSZ);

  prep_w<<<9, 64>>>(wgt);
  dim3 grid(2, 256, 16);   // (w-half, h, b) = 8192 CTAs
  conv_mma<<<grid, 256, SMEMSZ>>>(x, bias, out);
}